// round 2
// baseline (speedup 1.0000x reference)
#include <cuda_runtime.h>
#include <math.h>

// Problem constants
constexpr int L_  = 4;
constexpr int B_  = 4;
constexpr int N_  = 2048;
constexpr int D_  = 512;
constexpr int H_  = 8;
constexpr int HD_ = 64;
constexpr int M_  = B_ * N_;          // 8192 rows
constexpr float SCALE = 0.04419417382415922f;  // 1/sqrt(512)  (reference uses D**-0.5)

// Scratch buffers (no cudaMalloc allowed)
__device__ float g_Y[M_ * D_];
__device__ float g_Q[M_ * D_];
__device__ float g_K[M_ * D_];
__device__ float g_V[M_ * D_];
__device__ float g_O[M_ * D_];
__device__ float g_T[M_ * D_];

// ---------------------------------------------------------------------------
// LayerNorm: one block per row (D=512), 128 threads x 4 elems
// ---------------------------------------------------------------------------
__global__ __launch_bounds__(128) void ln_kernel(
    const float* __restrict__ x, const float* __restrict__ g,
    const float* __restrict__ b, float* __restrict__ y)
{
    __shared__ float sred[4];
    const int row = blockIdx.x;
    const int t = threadIdx.x;
    const float* xr = x + (size_t)row * D_;

    float4 v = *(const float4*)&xr[t * 4];
    float s = v.x + v.y + v.z + v.w;
    #pragma unroll
    for (int o = 16; o > 0; o >>= 1) s += __shfl_xor_sync(0xffffffffu, s, o);
    if ((t & 31) == 0) sred[t >> 5] = s;
    __syncthreads();
    const float mean = (sred[0] + sred[1] + sred[2] + sred[3]) * (1.0f / D_);
    __syncthreads();

    const float d0 = v.x - mean, d1 = v.y - mean, d2 = v.z - mean, d3 = v.w - mean;
    float s2 = d0 * d0 + d1 * d1 + d2 * d2 + d3 * d3;
    #pragma unroll
    for (int o = 16; o > 0; o >>= 1) s2 += __shfl_xor_sync(0xffffffffu, s2, o);
    if ((t & 31) == 0) sred[t >> 5] = s2;
    __syncthreads();
    const float var = (sred[0] + sred[1] + sred[2] + sred[3]) * (1.0f / D_);
    const float r = rsqrtf(var + 1e-5f);

    float4 gv = *(const float4*)&g[t * 4];
    float4 bv = *(const float4*)&b[t * 4];
    float4 o;
    o.x = d0 * r * gv.x + bv.x;
    o.y = d1 * r * gv.y + bv.y;
    o.z = d2 * r * gv.z + bv.z;
    o.w = d3 * r * gv.w + bv.w;
    *(float4*)&y[(size_t)row * D_ + t * 4] = o;
}

// ---------------------------------------------------------------------------
// SGEMM: C[M_,512] = A[M_,512] @ W[512,512]  (+bias) (+gelu) (+residual)
// Tiles: BM=128, BN=64, BK=16; 256 threads; 8x4 per thread.
// ---------------------------------------------------------------------------
constexpr int BM = 128, BN = 64, BK = 16;

template <bool BIAS, bool RESID, bool GELU>
__global__ __launch_bounds__(256) void gemm_kernel(
    const float* __restrict__ A, const float* __restrict__ W,
    const float* __restrict__ bias, const float* __restrict__ resid,
    float* __restrict__ C)
{
    __shared__ float As[BK][BM];
    __shared__ float Bs[BK][BN];

    const int tid = threadIdx.x;
    const int m0 = blockIdx.y * BM;
    const int n0 = blockIdx.x * BN;
    const int ty = tid >> 4;   // 0..15 -> 8 rows each
    const int tx = tid & 15;   // 0..15 -> 4 cols each

    float acc[8][4] = {};

    for (int k0 = 0; k0 < D_; k0 += BK) {
        // A tile: 128x16 = 512 float4, 2 per thread, store transposed
        #pragma unroll
        for (int i = 0; i < 2; i++) {
            const int f = tid + i * 256;
            const int row = f >> 2;
            const int cs = (f & 3) << 2;
            float4 v = *(const float4*)&A[(size_t)(m0 + row) * D_ + k0 + cs];
            As[cs + 0][row] = v.x;
            As[cs + 1][row] = v.y;
            As[cs + 2][row] = v.z;
            As[cs + 3][row] = v.w;
        }
        // B tile: 16x64 = 256 float4, 1 per thread
        {
            const int kr = tid >> 4;
            const int ns = (tid & 15) << 2;
            *(float4*)&Bs[kr][ns] = *(const float4*)&W[(size_t)(k0 + kr) * D_ + n0 + ns];
        }
        __syncthreads();

        #pragma unroll
        for (int kk = 0; kk < BK; kk++) {
            float a[8], b[4];
            *(float4*)&a[0] = *(const float4*)&As[kk][ty * 8];
            *(float4*)&a[4] = *(const float4*)&As[kk][ty * 8 + 4];
            *(float4*)&b[0] = *(const float4*)&Bs[kk][tx * 4];
            #pragma unroll
            for (int i = 0; i < 8; i++)
                #pragma unroll
                for (int j = 0; j < 4; j++)
                    acc[i][j] += a[i] * b[j];
        }
        __syncthreads();
    }

    #pragma unroll
    for (int i = 0; i < 8; i++) {
        const int m = m0 + ty * 8 + i;
        #pragma unroll
        for (int j = 0; j < 4; j++) {
            const int n = n0 + tx * 4 + j;
            float v = acc[i][j];
            if (BIAS) v += bias[n];
            if (GELU) v = 0.5f * v * (1.0f + erff(v * 0.70710678118654752f));
            if (RESID) v += resid[(size_t)m * D_ + n];
            C[(size_t)m * D_ + n] = v;
        }
    }
}

// ---------------------------------------------------------------------------
// Flash attention: block = (64 query rows, one b*h). K/V tiles of 64.
// smem: Q^T[64][68], K^T[64][68], V[64][68], S[64][65], stats.
// ---------------------------------------------------------------------------
constexpr int ATTN_SMEM_FLOATS = 3 * 64 * 68 + 64 * 65 + 3 * 64;
constexpr int ATTN_SMEM_BYTES  = ATTN_SMEM_FLOATS * 4;   // 69632

__global__ __launch_bounds__(256) void attn_kernel(
    const float* __restrict__ Q, const float* __restrict__ K,
    const float* __restrict__ V, float* __restrict__ O)
{
    extern __shared__ float sm[];
    float* sQ = sm;                  // transposed: sQ[d*68 + r]
    float* sK = sQ + 64 * 68;        // transposed: sK[d*68 + c]
    float* sV = sK + 64 * 68;        // row-major:  sV[kk*68 + c]
    float* sS = sV + 64 * 68;        // sS[r*65 + c]
    float* sM = sS + 64 * 65;
    float* sL = sM + 64;
    float* sC = sL + 64;

    const int tid = threadIdx.x;
    const int ty = tid >> 4;         // row group (4 rows)
    const int tx = tid & 15;         // col group (4 cols)
    const int bh = blockIdx.y;
    const int b = bh >> 3, h = bh & 7;
    const int q0 = blockIdx.x * 64;

    const float* Qb = Q + (size_t)b * N_ * D_ + (size_t)h * HD_;
    const float* Kb = K + (size_t)b * N_ * D_ + (size_t)h * HD_;
    const float* Vb = V + (size_t)b * N_ * D_ + (size_t)h * HD_;

    // Load Q tile transposed, pre-scaled
    #pragma unroll
    for (int i = 0; i < 4; i++) {
        const int f = tid + i * 256;
        const int r = f >> 4;
        const int c = (f & 15) << 2;
        float4 v = *(const float4*)&Qb[(size_t)(q0 + r) * D_ + c];
        sQ[(c + 0) * 68 + r] = v.x * SCALE;
        sQ[(c + 1) * 68 + r] = v.y * SCALE;
        sQ[(c + 2) * 68 + r] = v.z * SCALE;
        sQ[(c + 3) * 68 + r] = v.w * SCALE;
    }
    if (tid < 64) { sM[tid] = -3.0e38f; sL[tid] = 0.0f; }
    float acc[4][4] = {};
    __syncthreads();

    for (int kt = 0; kt < N_ / 64; kt++) {
        const int k0 = kt * 64;
        // Load K (transposed) and V (row-major) tiles
        #pragma unroll
        for (int i = 0; i < 4; i++) {
            const int f = tid + i * 256;
            const int r = f >> 4;
            const int c = (f & 15) << 2;
            float4 kv = *(const float4*)&Kb[(size_t)(k0 + r) * D_ + c];
            sK[(c + 0) * 68 + r] = kv.x;
            sK[(c + 1) * 68 + r] = kv.y;
            sK[(c + 2) * 68 + r] = kv.z;
            sK[(c + 3) * 68 + r] = kv.w;
            *(float4*)&sV[r * 68 + c] = *(const float4*)&Vb[(size_t)(k0 + r) * D_ + c];
        }
        __syncthreads();

        // S = Q K^T (scaled via Q)
        float s[4][4] = {};
        #pragma unroll 8
        for (int d = 0; d < 64; d++) {
            float4 av = *(const float4*)&sQ[d * 68 + ty * 4];
            float4 bv = *(const float4*)&sK[d * 68 + tx * 4];
            const float a[4] = {av.x, av.y, av.z, av.w};
            const float bb[4] = {bv.x, bv.y, bv.z, bv.w};
            #pragma unroll
            for (int i = 0; i < 4; i++)
                #pragma unroll
                for (int j = 0; j < 4; j++)
                    s[i][j] += a[i] * bb[j];
        }
        #pragma unroll
        for (int i = 0; i < 4; i++)
            #pragma unroll
            for (int j = 0; j < 4; j++)
                sS[(ty * 4 + i) * 65 + tx * 4 + j] = s[i][j];
        __syncthreads();

        // Online softmax (one thread per row)
        if (tid < 64) {
            const int r = tid;
            float mo = sM[r];
            float mt = mo;
            #pragma unroll 8
            for (int c = 0; c < 64; c++) mt = fmaxf(mt, sS[r * 65 + c]);
            const float cf = expf(mo - mt);
            float lsum = 0.0f;
            #pragma unroll 8
            for (int c = 0; c < 64; c++) {
                const float p = expf(sS[r * 65 + c] - mt);
                sS[r * 65 + c] = p;
                lsum += p;
            }
            sM[r] = mt;
            sL[r] = sL[r] * cf + lsum;
            sC[r] = cf;
        }
        __syncthreads();

        // Rescale accumulator + accumulate P @ V
        float cf[4];
        #pragma unroll
        for (int i = 0; i < 4; i++) {
            cf[i] = sC[ty * 4 + i];
            #pragma unroll
            for (int j = 0; j < 4; j++) acc[i][j] *= cf[i];
        }
        #pragma unroll 8
        for (int kk = 0; kk < 64; kk++) {
            float4 vv = *(const float4*)&sV[kk * 68 + tx * 4];
            const float vb[4] = {vv.x, vv.y, vv.z, vv.w};
            float p[4];
            #pragma unroll
            for (int i = 0; i < 4; i++) p[i] = sS[(ty * 4 + i) * 65 + kk];
            #pragma unroll
            for (int i = 0; i < 4; i++)
                #pragma unroll
                for (int j = 0; j < 4; j++)
                    acc[i][j] += p[i] * vb[j];
        }
        __syncthreads();
    }

    float inv[4];
    #pragma unroll
    for (int i = 0; i < 4; i++) inv[i] = 1.0f / sL[ty * 4 + i];
    float* Ob = O + (size_t)b * N_ * D_ + (size_t)h * HD_;
    #pragma unroll
    for (int i = 0; i < 4; i++)
        #pragma unroll
        for (int j = 0; j < 4; j++)
            Ob[(size_t)(q0 + ty * 4 + i) * D_ + tx * 4 + j] = acc[i][j] * inv[i];
}

// ---------------------------------------------------------------------------
// Host driver
// ---------------------------------------------------------------------------
extern "C" void kernel_launch(void* const* d_in, const int* in_sizes, int n_in,
                              void* d_out, int out_size)
{
    const float* x    = (const float*)d_in[0];
    const float* Wq   = (const float*)d_in[1];
    const float* Wk   = (const float*)d_in[2];
    const float* Wv   = (const float*)d_in[3];
    const float* Wo   = (const float*)d_in[4];
    const float* bo   = (const float*)d_in[5];
    const float* ln1g = (const float*)d_in[6];
    const float* ln1b = (const float*)d_in[7];
    const float* W1   = (const float*)d_in[8];
    const float* b1   = (const float*)d_in[9];
    const float* W2   = (const float*)d_in[10];
    const float* b2   = (const float*)d_in[11];
    const float* ln2g = (const float*)d_in[12];
    const float* ln2b = (const float*)d_in[13];

    float* h = (float*)d_out;

    float *Y, *Qb, *Kb, *Vb, *Ob, *Tb;
    cudaGetSymbolAddress((void**)&Y,  g_Y);
    cudaGetSymbolAddress((void**)&Qb, g_Q);
    cudaGetSymbolAddress((void**)&Kb, g_K);
    cudaGetSymbolAddress((void**)&Vb, g_V);
    cudaGetSymbolAddress((void**)&Ob, g_O);
    cudaGetSymbolAddress((void**)&Tb, g_T);

    cudaFuncSetAttribute(attn_kernel, cudaFuncAttributeMaxDynamicSharedMemorySize,
                         ATTN_SMEM_BYTES);

    // h = x
    cudaMemcpyAsync(h, x, (size_t)M_ * D_ * sizeof(float),
                    cudaMemcpyDeviceToDevice, 0);

    const dim3 ggrid(D_ / BN, M_ / BM);   // (8, 64)
    const dim3 agrid(N_ / 64, B_ * H_);   // (32, 32)

    for (int l = 0; l < L_; l++) {
        const float* wq = Wq + (size_t)l * D_ * D_;
        const float* wk = Wk + (size_t)l * D_ * D_;
        const float* wv = Wv + (size_t)l * D_ * D_;
        const float* wo = Wo + (size_t)l * D_ * D_;
        const float* w1 = W1 + (size_t)l * D_ * D_;
        const float* w2 = W2 + (size_t)l * D_ * D_;
        const float* bo_l = bo + (size_t)l * D_;
        const float* b1_l = b1 + (size_t)l * D_;
        const float* b2_l = b2 + (size_t)l * D_;

        // Attention block
        ln_kernel<<<M_, 128>>>(h, ln1g + (size_t)l * D_, ln1b + (size_t)l * D_, Y);
        gemm_kernel<false, false, false><<<ggrid, 256>>>(Y, wq, nullptr, nullptr, Qb);
        gemm_kernel<false, false, false><<<ggrid, 256>>>(Y, wk, nullptr, nullptr, Kb);
        gemm_kernel<false, false, false><<<ggrid, 256>>>(Y, wv, nullptr, nullptr, Vb);
        attn_kernel<<<agrid, 256, ATTN_SMEM_BYTES>>>(Qb, Kb, Vb, Ob);
        gemm_kernel<true, true, false><<<ggrid, 256>>>(Ob, wo, bo_l, h, h);

        // FFN block
        ln_kernel<<<M_, 128>>>(h, ln2g + (size_t)l * D_, ln2b + (size_t)l * D_, Y);
        gemm_kernel<true, false, true><<<ggrid, 256>>>(Y, w1, b1_l, nullptr, Tb);
        gemm_kernel<true, true, false><<<ggrid, 256>>>(Tb, w2, b2_l, h, h);
    }
}

// round 7
// speedup vs baseline: 2.8638x; 2.8638x over previous
#include <cuda_runtime.h>
#include <cuda_bf16.h>
#include <math.h>
#include <cstdint>

// Problem constants
constexpr int L_  = 4;
constexpr int B_  = 4;
constexpr int N_  = 2048;
constexpr int D_  = 512;
constexpr int H_  = 8;
constexpr int HD_ = 64;
constexpr int M_  = B_ * N_;          // 8192 rows
constexpr float SCALE = 0.04419417382415922f;  // 1/sqrt(512)
constexpr float LOG2E = 1.4426950408889634f;

// Scratch buffers (no cudaMalloc allowed)
__device__ float g_Y[M_ * D_];
__device__ float g_Q[M_ * D_];
__device__ float g_K[M_ * D_];
__device__ float g_V[M_ * D_];
__device__ float g_O[M_ * D_];
__device__ float g_T[M_ * D_];
__device__ float g_Wt[6 * L_ * D_ * D_];   // transposed weights [slot][layer][N][K]

// ---------------------------------------------------------------------------
// mma.sync / ldmatrix helpers (arch-agnostic PTX, works at compute_103)
// ---------------------------------------------------------------------------
__device__ __forceinline__ uint32_t s2u(const void* p) {
    uint32_t a;
    asm("{ .reg .u64 t; cvta.to.shared.u64 t, %1; cvt.u32.u64 %0, t; }" : "=r"(a) : "l"(p));
    return a;
}

__device__ __forceinline__ void ldm4(uint32_t* r, uint32_t addr) {
    asm volatile("ldmatrix.sync.aligned.m8n8.x4.shared.b16 {%0,%1,%2,%3}, [%4];"
        : "=r"(r[0]), "=r"(r[1]), "=r"(r[2]), "=r"(r[3]) : "r"(addr));
}
__device__ __forceinline__ void ldm4t(uint32_t* r, uint32_t addr) {
    asm volatile("ldmatrix.sync.aligned.m8n8.x4.trans.shared.b16 {%0,%1,%2,%3}, [%4];"
        : "=r"(r[0]), "=r"(r[1]), "=r"(r[2]), "=r"(r[3]) : "r"(addr));
}

// D(f32) += A(bf16) * B(bf16):  m16n8k16, A row-major, B col-major
__device__ __forceinline__ void mma16816(float* d, const uint32_t* a, uint32_t b0, uint32_t b1) {
    asm volatile("mma.sync.aligned.m16n8k16.row.col.f32.bf16.bf16.f32 "
        "{%0,%1,%2,%3}, {%4,%5,%6,%7}, {%8,%9}, {%0,%1,%2,%3};"
        : "+f"(d[0]), "+f"(d[1]), "+f"(d[2]), "+f"(d[3])
        : "r"(a[0]), "r"(a[1]), "r"(a[2]), "r"(a[3]), "r"(b0), "r"(b1));
}

__device__ __forceinline__ uint32_t packbf(float x, float y) {
    __nv_bfloat162 v = __floats2bfloat162_rn(x, y);
    return *(uint32_t*)&v;
}
__device__ __forceinline__ float fast_exp2(float x) {
    float y; asm("ex2.approx.f32 %0, %1;" : "=f"(y) : "f"(x)); return y;
}

// ---------------------------------------------------------------------------
// Weight transpose: out[l][n][k] = in[l][k][n]   (512x512 per layer)
// ---------------------------------------------------------------------------
__global__ __launch_bounds__(256) void transpose_kernel(
    const float* __restrict__ in, float* __restrict__ out)
{
    __shared__ float t[32][33];
    const int l = blockIdx.z;
    const float* A = in + (size_t)l * D_ * D_;
    float* O = out + (size_t)l * D_ * D_;
    const int k0 = blockIdx.y * 32, n0 = blockIdx.x * 32;
    const int tx = threadIdx.x & 31, ty = threadIdx.x >> 5;
    #pragma unroll
    for (int i = 0; i < 32; i += 8)
        t[ty + i][tx] = A[(size_t)(k0 + ty + i) * D_ + n0 + tx];
    __syncthreads();
    #pragma unroll
    for (int i = 0; i < 32; i += 8)
        O[(size_t)(n0 + ty + i) * D_ + k0 + tx] = t[tx][ty + i];
}

// ---------------------------------------------------------------------------
// LayerNorm: one block per row (D=512), 128 threads x 4 elems
// ---------------------------------------------------------------------------
__global__ __launch_bounds__(128) void ln_kernel(
    const float* __restrict__ x, const float* __restrict__ g,
    const float* __restrict__ b, float* __restrict__ y)
{
    __shared__ float sred[4];
    const int row = blockIdx.x;
    const int t = threadIdx.x;
    const float* xr = x + (size_t)row * D_;

    float4 v = *(const float4*)&xr[t * 4];
    float s = v.x + v.y + v.z + v.w;
    #pragma unroll
    for (int o = 16; o > 0; o >>= 1) s += __shfl_xor_sync(0xffffffffu, s, o);
    if ((t & 31) == 0) sred[t >> 5] = s;
    __syncthreads();
    const float mean = (sred[0] + sred[1] + sred[2] + sred[3]) * (1.0f / D_);
    __syncthreads();

    const float d0 = v.x - mean, d1 = v.y - mean, d2 = v.z - mean, d3 = v.w - mean;
    float s2 = d0 * d0 + d1 * d1 + d2 * d2 + d3 * d3;
    #pragma unroll
    for (int o = 16; o > 0; o >>= 1) s2 += __shfl_xor_sync(0xffffffffu, s2, o);
    if ((t & 31) == 0) sred[t >> 5] = s2;
    __syncthreads();
    const float var = (sred[0] + sred[1] + sred[2] + sred[3]) * (1.0f / D_);
    const float r = rsqrtf(var + 1e-5f);

    float4 gv = *(const float4*)&g[t * 4];
    float4 bv = *(const float4*)&b[t * 4];
    float4 o;
    o.x = d0 * r * gv.x + bv.x;
    o.y = d1 * r * gv.y + bv.y;
    o.z = d2 * r * gv.z + bv.z;
    o.w = d3 * r * gv.w + bv.w;
    *(float4*)&y[(size_t)row * D_ + t * 4] = o;
}

// ---------------------------------------------------------------------------
// mma.sync GEMM: C[M_,512] = A[M_,512] @ W[512,512], W pre-transposed Wt[N][K].
// fp32 via bf16 split: D += Ah*Bh + Ah*Bl + Al*Bh.
// Block 128x128, BK=16, 8 warps (warp tile 64x32).
// ---------------------------------------------------------------------------
constexpr int GTM = 128, GTN = 128;

template <bool BIAS, bool RESID, bool GELU>
__global__ __launch_bounds__(256) void tgemm_kernel(
    const float* __restrict__ A, const float* __restrict__ Wt,
    const float* __restrict__ bias, const float* __restrict__ resid,
    float* __restrict__ C)
{
    __shared__ __nv_bfloat16 sAh[128][24], sAl[128][24];
    __shared__ __nv_bfloat16 sBh[128][24], sBl[128][24];

    const int tid = threadIdx.x;
    const int wid = tid >> 5, lane = tid & 31;
    const int m0 = blockIdx.y * GTM, n0 = blockIdx.x * GTN;
    const int wm = (wid >> 2) * 64, wn = (wid & 3) * 32;

    const int row = tid >> 1;            // 0..127  (2 threads per row)
    const int colq = (tid & 1) * 2;      // float4 index 0 or 2 -> two float4 each

    float d[4][4][4];
    #pragma unroll
    for (int mi = 0; mi < 4; mi++)
        #pragma unroll
        for (int j = 0; j < 4; j++)
            #pragma unroll
            for (int e = 0; e < 4; e++) d[mi][j][e] = 0.0f;

    const uint32_t sbAh = s2u(&sAh[0][0]), sbAl = s2u(&sAl[0][0]);
    const uint32_t sbBh = s2u(&sBh[0][0]), sbBl = s2u(&sBl[0][0]);
    const uint32_t lrow = lane & 15, lchunk = (lane >> 4) * 16;

    // prefetch k-chunk 0
    float4 ra0, ra1, rb0, rb1;
    {
        const float* Ap = A  + (size_t)(m0 + row) * D_ + colq * 4;
        const float* Bp = Wt + (size_t)(n0 + row) * D_ + colq * 4;
        ra0 = *(const float4*)Ap;       ra1 = *(const float4*)(Ap + 4);
        rb0 = *(const float4*)Bp;       rb1 = *(const float4*)(Bp + 4);
    }

    for (int it = 0; it < 32; it++) {
        // store current regs -> smem as hi/lo bf16
        {
            float v[8] = {ra0.x, ra0.y, ra0.z, ra0.w, ra1.x, ra1.y, ra1.z, ra1.w};
            float w[8] = {rb0.x, rb0.y, rb0.z, rb0.w, rb1.x, rb1.y, rb1.z, rb1.w};
            #pragma unroll
            for (int q = 0; q < 2; q++) {
                float hx = __bfloat162float(__float2bfloat16_rn(v[q*4+0]));
                float hy = __bfloat162float(__float2bfloat16_rn(v[q*4+1]));
                float hz = __bfloat162float(__float2bfloat16_rn(v[q*4+2]));
                float hw = __bfloat162float(__float2bfloat16_rn(v[q*4+3]));
                *(uint2*)&sAh[row][(colq+q)*4] = make_uint2(packbf(hx, hy), packbf(hz, hw));
                *(uint2*)&sAl[row][(colq+q)*4] = make_uint2(
                    packbf(v[q*4+0]-hx, v[q*4+1]-hy), packbf(v[q*4+2]-hz, v[q*4+3]-hw));
                float gx = __bfloat162float(__float2bfloat16_rn(w[q*4+0]));
                float gy = __bfloat162float(__float2bfloat16_rn(w[q*4+1]));
                float gz = __bfloat162float(__float2bfloat16_rn(w[q*4+2]));
                float gw = __bfloat162float(__float2bfloat16_rn(w[q*4+3]));
                *(uint2*)&sBh[row][(colq+q)*4] = make_uint2(packbf(gx, gy), packbf(gz, gw));
                *(uint2*)&sBl[row][(colq+q)*4] = make_uint2(
                    packbf(w[q*4+0]-gx, w[q*4+1]-gy), packbf(w[q*4+2]-gz, w[q*4+3]-gw));
            }
        }
        __syncthreads();

        // prefetch next k-chunk
        if (it + 1 < 32) {
            const int k0 = (it + 1) * 16;
            const float* Ap = A  + (size_t)(m0 + row) * D_ + k0 + colq * 4;
            const float* Bp = Wt + (size_t)(n0 + row) * D_ + k0 + colq * 4;
            ra0 = *(const float4*)Ap;   ra1 = *(const float4*)(Ap + 4);
            rb0 = *(const float4*)Bp;   rb1 = *(const float4*)(Bp + 4);
        }

        // ldmatrix operands
        uint32_t ah[4][4], al[4][4], bh[2][4], bl[2][4];
        #pragma unroll
        for (int mi = 0; mi < 4; mi++) {
            const uint32_t off = (wm + mi * 16 + lrow) * 48 + lchunk;
            ldm4(ah[mi], sbAh + off);
            ldm4(al[mi], sbAl + off);
        }
        #pragma unroll
        for (int p = 0; p < 2; p++) {
            const uint32_t off = (wn + p * 16 + lrow) * 48 + lchunk;
            ldm4(bh[p], sbBh + off);
            ldm4(bl[p], sbBl + off);
        }
        #pragma unroll
        for (int mi = 0; mi < 4; mi++)
            #pragma unroll
            for (int j = 0; j < 4; j++) {
                const int p = j >> 1, q = j & 1;
                mma16816(d[mi][j], ah[mi], bh[p][q], bh[p][q + 2]);
                mma16816(d[mi][j], ah[mi], bl[p][q], bl[p][q + 2]);
                mma16816(d[mi][j], al[mi], bh[p][q], bh[p][q + 2]);
            }
        __syncthreads();
    }

    // Epilogue: fragment -> gmem with fused ops
    #pragma unroll
    for (int mi = 0; mi < 4; mi++) {
        #pragma unroll
        for (int j = 0; j < 4; j++) {
            const int gm = m0 + wm + mi * 16 + (lane >> 2);
            const int gn = n0 + wn + j * 8 + (lane & 3) * 2;
            float2 bv = make_float2(0.f, 0.f);
            if (BIAS) bv = *(const float2*)&bias[gn];
            #pragma unroll
            for (int half = 0; half < 2; half++) {
                const int m = gm + half * 8;
                float x0 = d[mi][j][half * 2 + 0];
                float x1 = d[mi][j][half * 2 + 1];
                if (BIAS) { x0 += bv.x; x1 += bv.y; }
                if (GELU) {
                    x0 = 0.5f * x0 * (1.0f + erff(x0 * 0.70710678118654752f));
                    x1 = 0.5f * x1 * (1.0f + erff(x1 * 0.70710678118654752f));
                }
                if (RESID) {
                    const float2 rv = *(const float2*)&resid[(size_t)m * D_ + gn];
                    x0 += rv.x; x1 += rv.y;
                }
                *(float2*)&C[(size_t)m * D_ + gn] = make_float2(x0, x1);
            }
        }
    }
}

// ---------------------------------------------------------------------------
// Flash attention via mma.sync. Block: 128 q-rows, one (b,h); 8 warps x 16 rows.
// KV tiles of 64. QK^T in bf16x3 (exact logits), PV in bf16.
// Logits pre-scaled by SCALE*log2e; softmax via ex2.
// ---------------------------------------------------------------------------
constexpr int AQH = 0;
constexpr int AQL = AQH + 128 * 72 * 2;   // 18432
constexpr int AKH = AQL + 128 * 72 * 2;   // 36864
constexpr int AKL = AKH + 64 * 72 * 2;    // 46080
constexpr int AVV = AKL + 64 * 72 * 2;    // 55296
constexpr int ATTN_SMEM = AVV + 64 * 72 * 2;  // 64512

__global__ __launch_bounds__(256) void attn_kernel(
    const float* __restrict__ Q, const float* __restrict__ K,
    const float* __restrict__ V, float* __restrict__ O)
{
    extern __shared__ char smem[];
    const uint32_t sb = s2u(smem);
    const int tid = threadIdx.x;
    const int wid = tid >> 5, lane = tid & 31;
    const int wm = wid * 16;
    const int bh = blockIdx.y;
    const int b = bh >> 3, h = bh & 7;
    const int q0 = blockIdx.x * 128;

    const float* Qb = Q + (size_t)b * N_ * D_ + (size_t)h * HD_;
    const float* Kb = K + (size_t)b * N_ * D_ + (size_t)h * HD_;
    const float* Vb = V + (size_t)b * N_ * D_ + (size_t)h * HD_;

    const float qs = SCALE * LOG2E;

    // Load Q tile (128x64), scaled, split hi/lo
    #pragma unroll
    for (int i = 0; i < 8; i++) {
        const int f = tid + i * 256;
        const int r = f >> 4, cq = (f & 15) * 4;
        float4 v = *(const float4*)&Qb[(size_t)(q0 + r) * D_ + cq];
        v.x *= qs; v.y *= qs; v.z *= qs; v.w *= qs;
        const float hx = __bfloat162float(__float2bfloat16_rn(v.x));
        const float hy = __bfloat162float(__float2bfloat16_rn(v.y));
        const float hz = __bfloat162float(__float2bfloat16_rn(v.z));
        const float hw = __bfloat162float(__float2bfloat16_rn(v.w));
        *(uint2*)(smem + AQH + (r * 72 + cq) * 2) = make_uint2(packbf(hx, hy), packbf(hz, hw));
        *(uint2*)(smem + AQL + (r * 72 + cq) * 2) =
            make_uint2(packbf(v.x - hx, v.y - hy), packbf(v.z - hz, v.w - hw));
    }
    __syncthreads();

    // Per-warp Q fragments (persistent)
    const uint32_t lrow = lane & 15, lchunk = (lane >> 4) * 16;
    uint32_t qh[4][4], ql[4][4];
    #pragma unroll
    for (int kf = 0; kf < 4; kf++) {
        const uint32_t off = (wm + lrow) * 144 + lchunk + kf * 32;
        ldm4(qh[kf], sb + AQH + off);
        ldm4(ql[kf], sb + AQL + off);
    }
    __syncthreads();

    float o[8][4];
    #pragma unroll
    for (int j = 0; j < 8; j++)
        #pragma unroll
        for (int e = 0; e < 4; e++) o[j][e] = 0.0f;
    float mrow0 = -1e30f, mrow1 = -1e30f, lrow0 = 0.0f, lrow1 = 0.0f;

    for (int kt = 0; kt < N_ / 64; kt++) {
        const int k0 = kt * 64;
        // Load K (hi/lo) and V (bf16) tiles
        #pragma unroll
        for (int i = 0; i < 4; i++) {
            const int f = tid + i * 256;
            const int r = f >> 4, cq = (f & 15) * 4;
            float4 kv = *(const float4*)&Kb[(size_t)(k0 + r) * D_ + cq];
            const float hx = __bfloat162float(__float2bfloat16_rn(kv.x));
            const float hy = __bfloat162float(__float2bfloat16_rn(kv.y));
            const float hz = __bfloat162float(__float2bfloat16_rn(kv.z));
            const float hw = __bfloat162float(__float2bfloat16_rn(kv.w));
            *(uint2*)(smem + AKH + (r * 72 + cq) * 2) = make_uint2(packbf(hx, hy), packbf(hz, hw));
            *(uint2*)(smem + AKL + (r * 72 + cq) * 2) =
                make_uint2(packbf(kv.x - hx, kv.y - hy), packbf(kv.z - hz, kv.w - hw));
            float4 vv = *(const float4*)&Vb[(size_t)(k0 + r) * D_ + cq];
            *(uint2*)(smem + AVV + (r * 72 + cq) * 2) =
                make_uint2(packbf(vv.x, vv.y), packbf(vv.z, vv.w));
        }
        __syncthreads();

        // S = Q K^T  (3-pass split)
        float c[8][4];
        #pragma unroll
        for (int j = 0; j < 8; j++)
            #pragma unroll
            for (int e = 0; e < 4; e++) c[j][e] = 0.0f;
        #pragma unroll
        for (int kf = 0; kf < 4; kf++) {
            uint32_t kh[4][4], kl[4][4];
            #pragma unroll
            for (int g = 0; g < 4; g++) {
                const uint32_t off = (g * 16 + lrow) * 144 + lchunk + kf * 32;
                ldm4(kh[g], sb + AKH + off);
                ldm4(kl[g], sb + AKL + off);
            }
            #pragma unroll
            for (int g = 0; g < 4; g++)
                #pragma unroll
                for (int q = 0; q < 2; q++) {
                    const int j = g * 2 + q;
                    mma16816(c[j], qh[kf], kh[g][q], kh[g][q + 2]);
                    mma16816(c[j], qh[kf], kl[g][q], kl[g][q + 2]);
                    mma16816(c[j], ql[kf], kh[g][q], kh[g][q + 2]);
                }
        }

        // Online softmax (log2 domain). Rows: r0 = lane>>2, r1 = r0+8.
        float tm0 = -1e30f, tm1 = -1e30f;
        #pragma unroll
        for (int j = 0; j < 8; j++) {
            tm0 = fmaxf(tm0, fmaxf(c[j][0], c[j][1]));
            tm1 = fmaxf(tm1, fmaxf(c[j][2], c[j][3]));
        }
        tm0 = fmaxf(tm0, __shfl_xor_sync(0xffffffffu, tm0, 1));
        tm0 = fmaxf(tm0, __shfl_xor_sync(0xffffffffu, tm0, 2));
        tm1 = fmaxf(tm1, __shfl_xor_sync(0xffffffffu, tm1, 1));
        tm1 = fmaxf(tm1, __shfl_xor_sync(0xffffffffu, tm1, 2));
        const float mn0 = fmaxf(mrow0, tm0), mn1 = fmaxf(mrow1, tm1);
        const float sc0 = fast_exp2(mrow0 - mn0), sc1 = fast_exp2(mrow1 - mn1);
        mrow0 = mn0; mrow1 = mn1;

        float rs0 = 0.0f, rs1 = 0.0f;
        uint32_t pa[4][4];
        #pragma unroll
        for (int j = 0; j < 8; j++) {
            const float p0 = fast_exp2(c[j][0] - mn0);
            const float p1 = fast_exp2(c[j][1] - mn0);
            const float p2 = fast_exp2(c[j][2] - mn1);
            const float p3 = fast_exp2(c[j][3] - mn1);
            rs0 += p0 + p1; rs1 += p2 + p3;
            // pack into A-fragment layout: frag kf=j/2, regs (j%2)*2 + {0,1}
            pa[j >> 1][(j & 1) * 2 + 0] = packbf(p0, p1);
            pa[j >> 1][(j & 1) * 2 + 1] = packbf(p2, p3);
        }
        rs0 += __shfl_xor_sync(0xffffffffu, rs0, 1);
        rs0 += __shfl_xor_sync(0xffffffffu, rs0, 2);
        rs1 += __shfl_xor_sync(0xffffffffu, rs1, 1);
        rs1 += __shfl_xor_sync(0xffffffffu, rs1, 2);
        lrow0 = lrow0 * sc0 + rs0;
        lrow1 = lrow1 * sc1 + rs1;

        // Rescale O accumulator
        #pragma unroll
        for (int j = 0; j < 8; j++) {
            o[j][0] *= sc0; o[j][1] *= sc0;
            o[j][2] *= sc1; o[j][3] *= sc1;
        }

        // O += P @ V  (V via trans ldmatrix from [token][hd])
        #pragma unroll
        for (int kf = 0; kf < 4; kf++) {
            uint32_t vb[4][4];
            #pragma unroll
            for (int g = 0; g < 4; g++)
                ldm4t(vb[g], sb + AVV + (kf * 16 + lrow) * 144 + lchunk + g * 32);
            #pragma unroll
            for (int g = 0; g < 4; g++) {
                mma16816(o[g * 2 + 0], pa[kf], vb[g][0], vb[g][1]);
                mma16816(o[g * 2 + 1], pa[kf], vb[g][2], vb[g][3]);
            }
        }
        __syncthreads();
    }

    // Normalize and write out
    const float inv0 = 1.0f / lrow0, inv1 = 1.0f / lrow1;
    float* Ob = O + (size_t)b * N_ * D_ + (size_t)h * HD_;
    const int r0 = q0 + wm + (lane >> 2);
    #pragma unroll
    for (int j = 0; j < 8; j++) {
        const int gn = j * 8 + (lane & 3) * 2;
        *(float2*)&Ob[(size_t)r0 * D_ + gn] = make_float2(o[j][0] * inv0, o[j][1] * inv0);
        *(float2*)&Ob[(size_t)(r0 + 8) * D_ + gn] = make_float2(o[j][2] * inv1, o[j][3] * inv1);
    }
}

// ---------------------------------------------------------------------------
// Host driver
// ---------------------------------------------------------------------------
extern "C" void kernel_launch(void* const* d_in, const int* in_sizes, int n_in,
                              void* d_out, int out_size)
{
    const float* x    = (const float*)d_in[0];
    const float* Wq   = (const float*)d_in[1];
    const float* Wk   = (const float*)d_in[2];
    const float* Wv   = (const float*)d_in[3];
    const float* Wo   = (const float*)d_in[4];
    const float* bo   = (const float*)d_in[5];
    const float* ln1g = (const float*)d_in[6];
    const float* ln1b = (const float*)d_in[7];
    const float* W1   = (const float*)d_in[8];
    const float* b1   = (const float*)d_in[9];
    const float* W2   = (const float*)d_in[10];
    const float* b2   = (const float*)d_in[11];
    const float* ln2g = (const float*)d_in[12];
    const float* ln2b = (const float*)d_in[13];

    float* h = (float*)d_out;

    float *Y, *Qb, *Kb, *Vb, *Ob, *Tb, *Wt;
    cudaGetSymbolAddress((void**)&Y,  g_Y);
    cudaGetSymbolAddress((void**)&Qb, g_Q);
    cudaGetSymbolAddress((void**)&Kb, g_K);
    cudaGetSymbolAddress((void**)&Vb, g_V);
    cudaGetSymbolAddress((void**)&Ob, g_O);
    cudaGetSymbolAddress((void**)&Tb, g_T);
    cudaGetSymbolAddress((void**)&Wt, g_Wt);

    cudaFuncSetAttribute(attn_kernel, cudaFuncAttributeMaxDynamicSharedMemorySize,
                         ATTN_SMEM);

    // Pre-transpose all weights: slot order Wq,Wk,Wv,Wo,W1,W2
    const size_t WSZ = (size_t)L_ * D_ * D_;
    const dim3 tgrid(16, 16, L_);
    transpose_kernel<<<tgrid, 256>>>(Wq, Wt + 0 * WSZ);
    transpose_kernel<<<tgrid, 256>>>(Wk, Wt + 1 * WSZ);
    transpose_kernel<<<tgrid, 256>>>(Wv, Wt + 2 * WSZ);
    transpose_kernel<<<tgrid, 256>>>(Wo, Wt + 3 * WSZ);
    transpose_kernel<<<tgrid, 256>>>(W1, Wt + 4 * WSZ);
    transpose_kernel<<<tgrid, 256>>>(W2, Wt + 5 * WSZ);

    // h = x
    cudaMemcpyAsync(h, x, (size_t)M_ * D_ * sizeof(float),
                    cudaMemcpyDeviceToDevice, 0);

    const dim3 ggrid(D_ / GTN, M_ / GTM);   // (4, 64) = 256 CTAs
    const dim3 agrid(N_ / 128, B_ * H_);    // (16, 32)

    for (int l = 0; l < L_; l++) {
        const float* wq = Wt + 0 * WSZ + (size_t)l * D_ * D_;
        const float* wk = Wt + 1 * WSZ + (size_t)l * D_ * D_;
        const float* wv = Wt + 2 * WSZ + (size_t)l * D_ * D_;
        const float* wo = Wt + 3 * WSZ + (size_t)l * D_ * D_;
        const float* w1 = Wt + 4 * WSZ + (size_t)l * D_ * D_;
        const float* w2 = Wt + 5 * WSZ + (size_t)l * D_ * D_;
        const float* bo_l = bo + (size_t)l * D_;
        const float* b1_l = b1 + (size_t)l * D_;
        const float* b2_l = b2 + (size_t)l * D_;

        // Attention block
        ln_kernel<<<M_, 128>>>(h, ln1g + (size_t)l * D_, ln1b + (size_t)l * D_, Y);
        tgemm_kernel<false, false, false><<<ggrid, 256>>>(Y, wq, nullptr, nullptr, Qb);
        tgemm_kernel<false, false, false><<<ggrid, 256>>>(Y, wk, nullptr, nullptr, Kb);
        tgemm_kernel<false, false, false><<<ggrid, 256>>>(Y, wv, nullptr, nullptr, Vb);
        attn_kernel<<<agrid, 256, ATTN_SMEM>>>(Qb, Kb, Vb, Ob);
        tgemm_kernel<true, true, false><<<ggrid, 256>>>(Ob, wo, bo_l, h, h);

        // FFN block
        ln_kernel<<<M_, 128>>>(h, ln2g + (size_t)l * D_, ln2b + (size_t)l * D_, Y);
        tgemm_kernel<true, false, true><<<ggrid, 256>>>(Y, w1, b1_l, nullptr, Tb);
        tgemm_kernel<true, true, false><<<ggrid, 256>>>(Tb, w2, b2_l, h, h);
    }
}

// round 9
// speedup vs baseline: 3.5851x; 1.2519x over previous
#include <cuda_runtime.h>
#include <cuda_bf16.h>
#include <cuda_fp16.h>
#include <math.h>
#include <cstdint>

// Problem constants
constexpr int L_  = 4;
constexpr int B_  = 4;
constexpr int N_  = 2048;
constexpr int D_  = 512;
constexpr int H_  = 8;
constexpr int HD_ = 64;
constexpr int M_  = B_ * N_;          // 8192 rows
constexpr float SCALE = 0.04419417382415922f;  // 1/sqrt(512)
constexpr float LOG2E = 1.4426950408889634f;
constexpr float QS    = SCALE * LOG2E;

// Scratch buffers (no cudaMalloc allowed)
__device__ __nv_bfloat16 g_Yh[M_ * D_], g_Yl[M_ * D_];
__device__ __nv_bfloat16 g_Oh[M_ * D_], g_Ol[M_ * D_];
__device__ __nv_bfloat16 g_Th[M_ * D_], g_Tl[M_ * D_];
__device__ __half        g_Qh[M_ * D_], g_Ql[M_ * D_];
__device__ __half        g_Kf[M_ * D_], g_Vf[M_ * D_];
__device__ __nv_bfloat16 g_Wh[6 * L_ * D_ * D_], g_Wl[6 * L_ * D_ * D_];

// ---------------------------------------------------------------------------
// PTX helpers (arch-agnostic: ldmatrix / mma.sync / cp.async)
// ---------------------------------------------------------------------------
__device__ __forceinline__ uint32_t s2u(const void* p) {
    uint32_t a;
    asm("{ .reg .u64 t; cvta.to.shared.u64 t, %1; cvt.u32.u64 %0, t; }" : "=r"(a) : "l"(p));
    return a;
}
__device__ __forceinline__ void ldm4(uint32_t* r, uint32_t addr) {
    asm volatile("ldmatrix.sync.aligned.m8n8.x4.shared.b16 {%0,%1,%2,%3}, [%4];"
        : "=r"(r[0]), "=r"(r[1]), "=r"(r[2]), "=r"(r[3]) : "r"(addr));
}
__device__ __forceinline__ void ldm4t(uint32_t* r, uint32_t addr) {
    asm volatile("ldmatrix.sync.aligned.m8n8.x4.trans.shared.b16 {%0,%1,%2,%3}, [%4];"
        : "=r"(r[0]), "=r"(r[1]), "=r"(r[2]), "=r"(r[3]) : "r"(addr));
}
__device__ __forceinline__ void mma_bf(float* d, const uint32_t* a, uint32_t b0, uint32_t b1) {
    asm volatile("mma.sync.aligned.m16n8k16.row.col.f32.bf16.bf16.f32 "
        "{%0,%1,%2,%3}, {%4,%5,%6,%7}, {%8,%9}, {%0,%1,%2,%3};"
        : "+f"(d[0]), "+f"(d[1]), "+f"(d[2]), "+f"(d[3])
        : "r"(a[0]), "r"(a[1]), "r"(a[2]), "r"(a[3]), "r"(b0), "r"(b1));
}
__device__ __forceinline__ void mma_fp(float* d, const uint32_t* a, uint32_t b0, uint32_t b1) {
    asm volatile("mma.sync.aligned.m16n8k16.row.col.f32.f16.f16.f32 "
        "{%0,%1,%2,%3}, {%4,%5,%6,%7}, {%8,%9}, {%0,%1,%2,%3};"
        : "+f"(d[0]), "+f"(d[1]), "+f"(d[2]), "+f"(d[3])
        : "r"(a[0]), "r"(a[1]), "r"(a[2]), "r"(a[3]), "r"(b0), "r"(b1));
}
__device__ __forceinline__ void cpa16(uint32_t s, const void* g) {
    asm volatile("cp.async.cg.shared.global [%0], [%1], 16;" :: "r"(s), "l"(g));
}
__device__ __forceinline__ void cpa_commit() { asm volatile("cp.async.commit_group;"); }
__device__ __forceinline__ void cpa_wait1() { asm volatile("cp.async.wait_group 1;"); }
__device__ __forceinline__ void cpa_wait0() { asm volatile("cp.async.wait_group 0;"); }

__device__ __forceinline__ uint32_t packbf(float x, float y) {
    __nv_bfloat162 v = __floats2bfloat162_rn(x, y);
    return *(uint32_t*)&v;
}
__device__ __forceinline__ uint32_t packhf(float x, float y) {
    __half2 v = __floats2half2_rn(x, y);
    return *(uint32_t*)&v;
}
__device__ __forceinline__ float fast_exp2(float x) {
    float y; asm("ex2.approx.f32 %0, %1;" : "=f"(y) : "f"(x)); return y;
}

// ---------------------------------------------------------------------------
// Weight prep: transpose + bf16 split. out[l][n][k] = split(in[l][k][n])
// ---------------------------------------------------------------------------
__global__ __launch_bounds__(256) void prep_w(
    const float* __restrict__ in, __nv_bfloat16* __restrict__ oh,
    __nv_bfloat16* __restrict__ ol)
{
    __shared__ float t[32][33];
    const int l = blockIdx.z;
    const float* A = in + (size_t)l * D_ * D_;
    const size_t ob = (size_t)l * D_ * D_;
    const int k0 = blockIdx.y * 32, n0 = blockIdx.x * 32;
    const int tx = threadIdx.x & 31, ty = threadIdx.x >> 5;
    #pragma unroll
    for (int i = 0; i < 32; i += 8)
        t[ty + i][tx] = A[(size_t)(k0 + ty + i) * D_ + n0 + tx];
    __syncthreads();
    #pragma unroll
    for (int i = 0; i < 32; i += 8) {
        const float v = t[tx][ty + i];
        const __nv_bfloat16 h = __float2bfloat16_rn(v);
        oh[ob + (size_t)(n0 + ty + i) * D_ + k0 + tx] = h;
        ol[ob + (size_t)(n0 + ty + i) * D_ + k0 + tx] =
            __float2bfloat16_rn(v - __bfloat162float(h));
    }
}

// ---------------------------------------------------------------------------
// LayerNorm: one block per row, writes bf16 hi/lo split
// ---------------------------------------------------------------------------
__global__ __launch_bounds__(128) void ln_kernel(
    const float* __restrict__ x, const float* __restrict__ g,
    const float* __restrict__ b, __nv_bfloat16* __restrict__ yh,
    __nv_bfloat16* __restrict__ yl)
{
    __shared__ float sred[4];
    const int row = blockIdx.x;
    const int t = threadIdx.x;
    const float* xr = x + (size_t)row * D_;

    float4 v = *(const float4*)&xr[t * 4];
    float s = v.x + v.y + v.z + v.w;
    #pragma unroll
    for (int o = 16; o > 0; o >>= 1) s += __shfl_xor_sync(0xffffffffu, s, o);
    if ((t & 31) == 0) sred[t >> 5] = s;
    __syncthreads();
    const float mean = (sred[0] + sred[1] + sred[2] + sred[3]) * (1.0f / D_);
    __syncthreads();

    const float d0 = v.x - mean, d1 = v.y - mean, d2 = v.z - mean, d3 = v.w - mean;
    float s2 = d0 * d0 + d1 * d1 + d2 * d2 + d3 * d3;
    #pragma unroll
    for (int o = 16; o > 0; o >>= 1) s2 += __shfl_xor_sync(0xffffffffu, s2, o);
    if ((t & 31) == 0) sred[t >> 5] = s2;
    __syncthreads();
    const float var = (sred[0] + sred[1] + sred[2] + sred[3]) * (1.0f / D_);
    const float r = rsqrtf(var + 1e-5f);

    float4 gv = *(const float4*)&g[t * 4];
    float4 bv = *(const float4*)&b[t * 4];
    float o0 = d0 * r * gv.x + bv.x;
    float o1 = d1 * r * gv.y + bv.y;
    float o2 = d2 * r * gv.z + bv.z;
    float o3 = d3 * r * gv.w + bv.w;
    const float h0 = __bfloat162float(__float2bfloat16_rn(o0));
    const float h1 = __bfloat162float(__float2bfloat16_rn(o1));
    const float h2 = __bfloat162float(__float2bfloat16_rn(o2));
    const float h3 = __bfloat162float(__float2bfloat16_rn(o3));
    const size_t o = (size_t)row * D_ + t * 4;
    *(uint2*)&yh[o] = make_uint2(packbf(h0, h1), packbf(h2, h3));
    *(uint2*)&yl[o] = make_uint2(packbf(o0 - h0, o1 - h1), packbf(o2 - h2, o3 - h3));
}

// ---------------------------------------------------------------------------
// GEMM: C = A @ W^T with pre-split bf16 operands (Ah+Al)(Bh+Bl), 3-pass.
// Block 128x128, BK=32, 2-stage cp.async pipeline, 8 warps (64x32 warp tile).
// ---------------------------------------------------------------------------
constexpr int GP  = 80;          // smem row pitch bytes (32 bf16 + pad)
constexpr int OPB = 128 * GP;    // bytes per operand per stage (10240)
constexpr int STG = 4 * OPB;     // stage size (40960)
constexpr int GSMEM = 2 * STG;   // 81920

enum { MODE_F32R = 0, MODE_BF16S = 1, MODE_F16SQ = 2, MODE_F16 = 3 };

template <int MODE, bool BIAS, bool GELU_>
__global__ __launch_bounds__(256) void tgemm_kernel(
    const __nv_bfloat16* __restrict__ Ah, const __nv_bfloat16* __restrict__ Al,
    const __nv_bfloat16* __restrict__ Bh, const __nv_bfloat16* __restrict__ Bl,
    const float* __restrict__ bias, const float* __restrict__ resid,
    void* __restrict__ out1, void* __restrict__ out2)
{
    extern __shared__ char smem[];
    const uint32_t sb = s2u(smem);
    const int tid = threadIdx.x;
    const int wid = tid >> 5, lane = tid & 31;
    const int m0 = blockIdx.y * 128, n0 = blockIdx.x * 128;
    const int wm = (wid >> 2) * 64, wn = (wid & 3) * 32;
    const uint32_t lrow = lane & 15, lch = (lane >> 4) * 16;

    float d[4][4][4];
    #pragma unroll
    for (int mi = 0; mi < 4; mi++)
        #pragma unroll
        for (int j = 0; j < 4; j++)
            #pragma unroll
            for (int e = 0; e < 4; e++) d[mi][j][e] = 0.0f;

    auto ld_stage = [&](int it, int st) {
        const int k0 = it * 32;
        const uint32_t sbase = sb + st * STG;
        #pragma unroll
        for (int c = 0; c < 8; c++) {
            const int op = c >> 1;
            const int idx = (c & 1) * 256 + tid;
            const int row = idx >> 2, seg = idx & 3;
            const __nv_bfloat16* gp;
            if (op == 0)      gp = Ah + (size_t)(m0 + row) * D_ + k0 + seg * 8;
            else if (op == 1) gp = Al + (size_t)(m0 + row) * D_ + k0 + seg * 8;
            else if (op == 2) gp = Bh + (size_t)(n0 + row) * D_ + k0 + seg * 8;
            else              gp = Bl + (size_t)(n0 + row) * D_ + k0 + seg * 8;
            cpa16(sbase + op * OPB + row * GP + seg * 16, gp);
        }
    };

    ld_stage(0, 0); cpa_commit();
    ld_stage(1, 1); cpa_commit();

    for (int it = 0; it < 16; it++) {
        if (it == 15) cpa_wait0(); else cpa_wait1();
        __syncthreads();

        const uint32_t base = sb + (it & 1) * STG;
        #pragma unroll
        for (int kf = 0; kf < 2; kf++) {
            uint32_t ah[4][4], al[4][4], bh2[2][4], bl2[2][4];
            #pragma unroll
            for (int mi = 0; mi < 4; mi++) {
                const uint32_t off = (wm + mi * 16 + lrow) * GP + kf * 32 + lch;
                ldm4(ah[mi], base + 0 * OPB + off);
                ldm4(al[mi], base + 1 * OPB + off);
            }
            #pragma unroll
            for (int p = 0; p < 2; p++) {
                const uint32_t off = (wn + p * 16 + lrow) * GP + kf * 32 + lch;
                ldm4(bh2[p], base + 2 * OPB + off);
                ldm4(bl2[p], base + 3 * OPB + off);
            }
            #pragma unroll
            for (int mi = 0; mi < 4; mi++)
                #pragma unroll
                for (int j = 0; j < 4; j++) {
                    const int p = j >> 1, q = j & 1;
                    mma_bf(d[mi][j], ah[mi], bh2[p][q], bh2[p][q + 2]);
                    mma_bf(d[mi][j], ah[mi], bl2[p][q], bl2[p][q + 2]);
                    mma_bf(d[mi][j], al[mi], bh2[p][q], bh2[p][q + 2]);
                }
        }
        __syncthreads();
        if (it + 2 < 16) { ld_stage(it + 2, it & 1); cpa_commit(); }
    }

    // Fused epilogue
    #pragma unroll
    for (int mi = 0; mi < 4; mi++) {
        #pragma unroll
        for (int j = 0; j < 4; j++) {
            const int gm = m0 + wm + mi * 16 + (lane >> 2);
            const int gn = n0 + wn + j * 8 + (lane & 3) * 2;
            float2 bv = make_float2(0.f, 0.f);
            if (BIAS) bv = *(const float2*)&bias[gn];
            #pragma unroll
            for (int half = 0; half < 2; half++) {
                const int m = gm + half * 8;
                float x0 = d[mi][j][half * 2 + 0];
                float x1 = d[mi][j][half * 2 + 1];
                if (BIAS) { x0 += bv.x; x1 += bv.y; }
                if (GELU_) {
                    x0 = 0.5f * x0 * (1.0f + erff(x0 * 0.70710678118654752f));
                    x1 = 0.5f * x1 * (1.0f + erff(x1 * 0.70710678118654752f));
                }
                const size_t o = (size_t)m * D_ + gn;
                if (MODE == MODE_F32R) {
                    const float2 rv = *(const float2*)&resid[o];
                    *(float2*)&((float*)out1)[o] = make_float2(x0 + rv.x, x1 + rv.y);
                } else if (MODE == MODE_BF16S) {
                    const float h0 = __bfloat162float(__float2bfloat16_rn(x0));
                    const float h1 = __bfloat162float(__float2bfloat16_rn(x1));
                    *(uint32_t*)&((__nv_bfloat16*)out1)[o] = packbf(h0, h1);
                    *(uint32_t*)&((__nv_bfloat16*)out2)[o] = packbf(x0 - h0, x1 - h1);
                } else if (MODE == MODE_F16SQ) {
                    const float v0 = x0 * QS, v1 = x1 * QS;
                    const float h0 = __half2float(__float2half_rn(v0));
                    const float h1 = __half2float(__float2half_rn(v1));
                    *(uint32_t*)&((__half*)out1)[o] = packhf(h0, h1);
                    *(uint32_t*)&((__half*)out2)[o] = packhf(v0 - h0, v1 - h1);
                } else {  // MODE_F16
                    *(uint32_t*)&((__half*)out1)[o] = packhf(x0, x1);
                }
            }
        }
    }
}

// ---------------------------------------------------------------------------
// Flash attention, fp16 mma. 128 q-rows per CTA, KV tiles 64, cp.async 2-stage.
// QK^T: 2-pass (Qh+Ql fp16-split, K single fp16). PV: single fp16.
// Q pre-scaled by SCALE*log2e at QKV-GEMM epilogue. Output: bf16 hi/lo.
// ---------------------------------------------------------------------------
constexpr int AP   = 144;                 // smem pitch bytes (64 fp16 + pad)
constexpr int AQH  = 0;                   // 128*144 = 18432
constexpr int AQL  = 18432;
constexpr int AKV0 = 36864;               // stage: K (64*144) + V (64*144)
constexpr int AKV1 = 36864 + 18432;
constexpr int ATTN_SMEM = AKV1 + 18432;   // 73728

__global__ __launch_bounds__(256) void attn_kernel(
    const __half* __restrict__ Qh, const __half* __restrict__ Ql,
    const __half* __restrict__ Kf, const __half* __restrict__ Vf,
    __nv_bfloat16* __restrict__ Ohp, __nv_bfloat16* __restrict__ Olp)
{
    extern __shared__ char smem[];
    const uint32_t sb = s2u(smem);
    const int tid = threadIdx.x;
    const int wid = tid >> 5, lane = tid & 31;
    const int wm = wid * 16;
    const int bh = blockIdx.y;
    const int b = bh >> 3, h = bh & 7;
    const int q0 = blockIdx.x * 128;
    const uint32_t lrow = lane & 15, lch = (lane >> 4) * 16;

    const __half* Qhb = Qh + (size_t)b * N_ * D_ + (size_t)h * HD_;
    const __half* Qlb = Ql + (size_t)b * N_ * D_ + (size_t)h * HD_;
    const __half* Kb  = Kf + (size_t)b * N_ * D_ + (size_t)h * HD_;
    const __half* Vb  = Vf + (size_t)b * N_ * D_ + (size_t)h * HD_;

    auto ld_kv = [&](int kt, uint32_t stbase) {
        const int k0 = kt * 64;
        #pragma unroll
        for (int c = 0; c < 4; c++) {
            const int idx = (c & 1) * 256 + tid;
            const int row = idx >> 3, seg = idx & 7;
            const __half* gp = (c < 2 ? Kb : Vb) + (size_t)(k0 + row) * D_ + seg * 8;
            cpa16(stbase + (c < 2 ? 0 : 9216) + row * AP + seg * 16, gp);
        }
    };

    // issue KV tile 0, then stage Q
    ld_kv(0, sb + AKV0); cpa_commit();

    #pragma unroll
    for (int i = 0; i < 8; i++) {
        const int f = tid + i * 256;        // 2048 chunks: 2 arrays x 128 rows x 8 segs
        const int arr = f >> 10, rem = f & 1023;
        const int r = rem >> 3, seg = rem & 7;
        const __half* src = (arr == 0 ? Qhb : Qlb) + (size_t)(q0 + r) * D_ + seg * 8;
        *(uint4*)(smem + (arr == 0 ? AQH : AQL) + r * AP + seg * 16) = *(const uint4*)src;
    }
    __syncthreads();

    uint32_t qh[4][4], ql[4][4];
    #pragma unroll
    for (int kf = 0; kf < 4; kf++) {
        const uint32_t off = (wm + lrow) * AP + kf * 32 + lch;
        ldm4(qh[kf], sb + AQH + off);
        ldm4(ql[kf], sb + AQL + off);
    }

    float o[8][4];
    #pragma unroll
    for (int j = 0; j < 8; j++)
        #pragma unroll
        for (int e = 0; e < 4; e++) o[j][e] = 0.0f;
    float mrow0 = -1e30f, mrow1 = -1e30f, lsum0 = 0.0f, lsum1 = 0.0f;

    constexpr int NT = N_ / 64;   // 32
    for (int kt = 0; kt < NT; kt++) {
        if (kt + 1 < NT) { ld_kv(kt + 1, sb + ((kt + 1) & 1 ? AKV1 : AKV0)); cpa_commit(); }
        if (kt + 1 < NT) cpa_wait1(); else cpa_wait0();
        __syncthreads();

        const uint32_t kvb = sb + ((kt & 1) ? AKV1 : AKV0);

        // S = Q K^T (2-pass fp16 split)
        float c[8][4];
        #pragma unroll
        for (int j = 0; j < 8; j++)
            #pragma unroll
            for (int e = 0; e < 4; e++) c[j][e] = 0.0f;
        #pragma unroll
        for (int kf = 0; kf < 4; kf++) {
            uint32_t kh[4][4];
            #pragma unroll
            for (int g = 0; g < 4; g++)
                ldm4(kh[g], kvb + (g * 16 + lrow) * AP + kf * 32 + lch);
            #pragma unroll
            for (int g = 0; g < 4; g++)
                #pragma unroll
                for (int q = 0; q < 2; q++) {
                    const int j = g * 2 + q;
                    mma_fp(c[j], qh[kf], kh[g][q], kh[g][q + 2]);
                    mma_fp(c[j], ql[kf], kh[g][q], kh[g][q + 2]);
                }
        }

        // Online softmax in log2 domain
        float tm0 = -1e30f, tm1 = -1e30f;
        #pragma unroll
        for (int j = 0; j < 8; j++) {
            tm0 = fmaxf(tm0, fmaxf(c[j][0], c[j][1]));
            tm1 = fmaxf(tm1, fmaxf(c[j][2], c[j][3]));
        }
        tm0 = fmaxf(tm0, __shfl_xor_sync(0xffffffffu, tm0, 1));
        tm0 = fmaxf(tm0, __shfl_xor_sync(0xffffffffu, tm0, 2));
        tm1 = fmaxf(tm1, __shfl_xor_sync(0xffffffffu, tm1, 1));
        tm1 = fmaxf(tm1, __shfl_xor_sync(0xffffffffu, tm1, 2));
        const float mn0 = fmaxf(mrow0, tm0), mn1 = fmaxf(mrow1, tm1);
        const float sc0 = fast_exp2(mrow0 - mn0), sc1 = fast_exp2(mrow1 - mn1);
        mrow0 = mn0; mrow1 = mn1;

        float rs0 = 0.0f, rs1 = 0.0f;
        uint32_t pa[4][4];
        #pragma unroll
        for (int j = 0; j < 8; j++) {
            const float p0 = fast_exp2(c[j][0] - mn0);
            const float p1 = fast_exp2(c[j][1] - mn0);
            const float p2 = fast_exp2(c[j][2] - mn1);
            const float p3 = fast_exp2(c[j][3] - mn1);
            rs0 += p0 + p1; rs1 += p2 + p3;
            pa[j >> 1][(j & 1) * 2 + 0] = packhf(p0, p1);
            pa[j >> 1][(j & 1) * 2 + 1] = packhf(p2, p3);
        }
        rs0 += __shfl_xor_sync(0xffffffffu, rs0, 1);
        rs0 += __shfl_xor_sync(0xffffffffu, rs0, 2);
        rs1 += __shfl_xor_sync(0xffffffffu, rs1, 1);
        rs1 += __shfl_xor_sync(0xffffffffu, rs1, 2);
        lsum0 = lsum0 * sc0 + rs0;
        lsum1 = lsum1 * sc1 + rs1;

        #pragma unroll
        for (int j = 0; j < 8; j++) {
            o[j][0] *= sc0; o[j][1] *= sc0;
            o[j][2] *= sc1; o[j][3] *= sc1;
        }

        // O += P @ V
        #pragma unroll
        for (int kf = 0; kf < 4; kf++) {
            uint32_t vb[4][4];
            #pragma unroll
            for (int g = 0; g < 4; g++)
                ldm4t(vb[g], kvb + 9216 + (kf * 16 + lrow) * AP + g * 32 + lch);
            #pragma unroll
            for (int g = 0; g < 4; g++) {
                mma_fp(o[g * 2 + 0], pa[kf], vb[g][0], vb[g][1]);
                mma_fp(o[g * 2 + 1], pa[kf], vb[g][2], vb[g][3]);
            }
        }
        __syncthreads();
    }

    // Normalize, split to bf16 hi/lo, write
    const float inv0 = 1.0f / lsum0, inv1 = 1.0f / lsum1;
    const size_t obase = (size_t)b * N_ * D_ + (size_t)h * HD_;
    const int r0 = q0 + wm + (lane >> 2);
    #pragma unroll
    for (int j = 0; j < 8; j++) {
        const int gn = j * 8 + (lane & 3) * 2;
        #pragma unroll
        for (int half = 0; half < 2; half++) {
            const float inv = half ? inv1 : inv0;
            const float x0 = o[j][half * 2 + 0] * inv;
            const float x1 = o[j][half * 2 + 1] * inv;
            const float h0 = __bfloat162float(__float2bfloat16_rn(x0));
            const float h1 = __bfloat162float(__float2bfloat16_rn(x1));
            const size_t off = obase + (size_t)(r0 + half * 8) * D_ + gn;
            *(uint32_t*)&Ohp[off] = packbf(h0, h1);
            *(uint32_t*)&Olp[off] = packbf(x0 - h0, x1 - h1);
        }
    }
}

// ---------------------------------------------------------------------------
// Host driver
// ---------------------------------------------------------------------------
extern "C" void kernel_launch(void* const* d_in, const int* in_sizes, int n_in,
                              void* d_out, int out_size)
{
    const float* x    = (const float*)d_in[0];
    const float* Wq   = (const float*)d_in[1];
    const float* Wk   = (const float*)d_in[2];
    const float* Wv   = (const float*)d_in[3];
    const float* Wo   = (const float*)d_in[4];
    const float* bo   = (const float*)d_in[5];
    const float* ln1g = (const float*)d_in[6];
    const float* ln1b = (const float*)d_in[7];
    const float* W1   = (const float*)d_in[8];
    const float* b1   = (const float*)d_in[9];
    const float* W2   = (const float*)d_in[10];
    const float* b2   = (const float*)d_in[11];
    const float* ln2g = (const float*)d_in[12];
    const float* ln2b = (const float*)d_in[13];

    float* h = (float*)d_out;

    __nv_bfloat16 *Yh, *Yl, *Oh, *Ol, *Th, *Tl, *Wh, *Wl;
    __half *Qh, *Ql, *Kf, *Vf;
    cudaGetSymbolAddress((void**)&Yh, g_Yh); cudaGetSymbolAddress((void**)&Yl, g_Yl);
    cudaGetSymbolAddress((void**)&Oh, g_Oh); cudaGetSymbolAddress((void**)&Ol, g_Ol);
    cudaGetSymbolAddress((void**)&Th, g_Th); cudaGetSymbolAddress((void**)&Tl, g_Tl);
    cudaGetSymbolAddress((void**)&Qh, g_Qh); cudaGetSymbolAddress((void**)&Ql, g_Ql);
    cudaGetSymbolAddress((void**)&Kf, g_Kf); cudaGetSymbolAddress((void**)&Vf, g_Vf);
    cudaGetSymbolAddress((void**)&Wh, g_Wh); cudaGetSymbolAddress((void**)&Wl, g_Wl);

    cudaFuncSetAttribute(attn_kernel, cudaFuncAttributeMaxDynamicSharedMemorySize, ATTN_SMEM);
    cudaFuncSetAttribute(tgemm_kernel<MODE_F16SQ, false, false>,
                         cudaFuncAttributeMaxDynamicSharedMemorySize, GSMEM);
    cudaFuncSetAttribute(tgemm_kernel<MODE_F16, false, false>,
                         cudaFuncAttributeMaxDynamicSharedMemorySize, GSMEM);
    cudaFuncSetAttribute(tgemm_kernel<MODE_F32R, true, false>,
                         cudaFuncAttributeMaxDynamicSharedMemorySize, GSMEM);
    cudaFuncSetAttribute(tgemm_kernel<MODE_BF16S, true, true>,
                         cudaFuncAttributeMaxDynamicSharedMemorySize, GSMEM);

    // Weight prep: transpose + bf16 split. Slots: Wq,Wk,Wv,Wo,W1,W2
    const size_t WSZ = (size_t)L_ * D_ * D_;
    const dim3 tgrid(16, 16, L_);
    prep_w<<<tgrid, 256>>>(Wq, Wh + 0 * WSZ, Wl + 0 * WSZ);
    prep_w<<<tgrid, 256>>>(Wk, Wh + 1 * WSZ, Wl + 1 * WSZ);
    prep_w<<<tgrid, 256>>>(Wv, Wh + 2 * WSZ, Wl + 2 * WSZ);
    prep_w<<<tgrid, 256>>>(Wo, Wh + 3 * WSZ, Wl + 3 * WSZ);
    prep_w<<<tgrid, 256>>>(W1, Wh + 4 * WSZ, Wl + 4 * WSZ);
    prep_w<<<tgrid, 256>>>(W2, Wh + 5 * WSZ, Wl + 5 * WSZ);

    cudaMemcpyAsync(h, x, (size_t)M_ * D_ * sizeof(float), cudaMemcpyDeviceToDevice, 0);

    const dim3 ggrid(D_ / 128, M_ / 128);   // (4, 64)
    const dim3 agrid(N_ / 128, B_ * H_);    // (16, 32)

    for (int l = 0; l < L_; l++) {
        const __nv_bfloat16* wqh = Wh + 0 * WSZ + (size_t)l * D_ * D_;
        const __nv_bfloat16* wql = Wl + 0 * WSZ + (size_t)l * D_ * D_;
        const __nv_bfloat16* wkh = Wh + 1 * WSZ + (size_t)l * D_ * D_;
        const __nv_bfloat16* wkl = Wl + 1 * WSZ + (size_t)l * D_ * D_;
        const __nv_bfloat16* wvh = Wh + 2 * WSZ + (size_t)l * D_ * D_;
        const __nv_bfloat16* wvl = Wl + 2 * WSZ + (size_t)l * D_ * D_;
        const __nv_bfloat16* woh = Wh + 3 * WSZ + (size_t)l * D_ * D_;
        const __nv_bfloat16* wol = Wl + 3 * WSZ + (size_t)l * D_ * D_;
        const __nv_bfloat16* w1h = Wh + 4 * WSZ + (size_t)l * D_ * D_;
        const __nv_bfloat16* w1l = Wl + 4 * WSZ + (size_t)l * D_ * D_;
        const __nv_bfloat16* w2h = Wh + 5 * WSZ + (size_t)l * D_ * D_;
        const __nv_bfloat16* w2l = Wl + 5 * WSZ + (size_t)l * D_ * D_;
        const float* bo_l = bo + (size_t)l * D_;
        const float* b1_l = b1 + (size_t)l * D_;
        const float* b2_l = b2 + (size_t)l * D_;

        // Attention block
        ln_kernel<<<M_, 128>>>(h, ln1g + (size_t)l * D_, ln1b + (size_t)l * D_, Yh, Yl);
        tgemm_kernel<MODE_F16SQ, false, false><<<ggrid, 256, GSMEM>>>(
            Yh, Yl, wqh, wql, nullptr, nullptr, Qh, Ql);
        tgemm_kernel<MODE_F16, false, false><<<ggrid, 256, GSMEM>>>(
            Yh, Yl, wkh, wkl, nullptr, nullptr, Kf, nullptr);
        tgemm_kernel<MODE_F16, false, false><<<ggrid, 256, GSMEM>>>(
            Yh, Yl, wvh, wvl, nullptr, nullptr, Vf, nullptr);
        attn_kernel<<<agrid, 256, ATTN_SMEM>>>(Qh, Ql, Kf, Vf, Oh, Ol);
        tgemm_kernel<MODE_F32R, true, false><<<ggrid, 256, GSMEM>>>(
            Oh, Ol, woh, wol, bo_l, h, h, nullptr);

        // FFN block
        ln_kernel<<<M_, 128>>>(h, ln2g + (size_t)l * D_, ln2b + (size_t)l * D_, Yh, Yl);
        tgemm_kernel<MODE_BF16S, true, true><<<ggrid, 256, GSMEM>>>(
            Yh, Yl, w1h, w1l, b1_l, nullptr, Th, Tl);
        tgemm_kernel<MODE_F32R, true, false><<<ggrid, 256, GSMEM>>>(
            Th, Tl, w2h, w2l, b2_l, h, h, nullptr);
    }
}